// round 2
// baseline (speedup 1.0000x reference)
#include <cuda_runtime.h>
#include <cuda_bf16.h>
#include <cstdint>

#define NPTS 100000
#define BSZ  8
#define CIMG 512
#define CPT  256
#define IMH  48
#define IMW  160
#define HW   (IMH*IMW)      /* 7680  */
#define NPIX (BSZ*HW)       /* 61440 */

// Scratch (device globals; no allocation in kernel_launch)
__device__ __nv_bfloat16 g_Wb[CPT * CIMG];                    // align_w in bf16, row-major (256,512)
__device__ __nv_bfloat16 g_pix[(size_t)NPIX * CPT];           // channel-last projected pixels, bf16

// ---------------------------------------------------------------------------
// Kernel 0: convert align_w (f32) -> bf16
// ---------------------------------------------------------------------------
__global__ void convW_kernel(const float* __restrict__ W) {
    int i = blockIdx.x * blockDim.x + threadIdx.x;
    if (i < CPT * CIMG) g_Wb[i] = __float2bfloat16(W[i]);
}

// ---------------------------------------------------------------------------
// Kernel 1: per-batch GEMM  pix_b(7680x256) = G_b^T(7680x512) @ W^T(512x256)
//   G_b(k, p) = img[b*512*7680 + k*7680 + p]  (pixel dim contiguous)
//   bf16 mma.sync m16n8k16, fp32 accumulate, bf16 output to g_pix.
//   Block tile: BM=128 pixels x BN=256 channels, BK=32. 8 warps (2m x 4n),
//   warp tile 64x64 -> 4x8 mma tiles, 128 f32 accum regs/thread.
// ---------------------------------------------------------------------------
#define BM 128
#define BN 256
#define BK 32

__global__ __launch_bounds__(256, 1)
void gemm_pix_kernel(const float* __restrict__ img) {
    __shared__ __nv_bfloat16 As[BK][BM + 8];   // [k][m], pad -> conflict-free ldmatrix.trans
    __shared__ __nv_bfloat16 Bs[BN][BK + 8];   // [n][k], pad -> conflict-free ldmatrix

    const int b  = blockIdx.z;
    const int p0 = blockIdx.x * BM;
    const float* gA = img + (size_t)b * CIMG * HW;

    const int tid  = threadIdx.x;
    const int lane = tid & 31;
    const int warp = tid >> 5;
    const int wm   = warp & 1;    // 0..1 -> m offset wm*64
    const int wn   = warp >> 1;   // 0..3 -> n offset wn*64

    float acc[4][8][4];
    #pragma unroll
    for (int i = 0; i < 4; i++)
        #pragma unroll
        for (int j = 0; j < 8; j++)
            #pragma unroll
            for (int k = 0; k < 4; k++) acc[i][j][k] = 0.f;

    for (int kt = 0; kt < CIMG; kt += BK) {
        // Load A tile: 32 k-rows x 128 pixels (f32 -> bf16), float4 per access
        #pragma unroll
        for (int i = 0; i < 4; i++) {
            int idx = tid + i * 256;          // 0..1023
            int kk  = idx >> 5;               // 0..31
            int m4  = (idx & 31) << 2;        // 0..124 step 4
            float4 v = *reinterpret_cast<const float4*>(gA + (size_t)(kt + kk) * HW + p0 + m4);
            As[kk][m4 + 0] = __float2bfloat16(v.x);
            As[kk][m4 + 1] = __float2bfloat16(v.y);
            As[kk][m4 + 2] = __float2bfloat16(v.z);
            As[kk][m4 + 3] = __float2bfloat16(v.w);
        }
        // Load B tile: 256 n-rows x 32 k (bf16), 8 bf16 (uint4) per access
        #pragma unroll
        for (int i = 0; i < 4; i++) {
            int idx = tid + i * 256;          // 0..1023
            int n   = idx >> 2;               // 0..255
            int k8  = (idx & 3) << 3;         // 0,8,16,24
            uint4 v = *reinterpret_cast<const uint4*>(&g_Wb[n * CIMG + kt + k8]);
            *reinterpret_cast<uint4*>(&Bs[n][k8]) = v;
        }
        __syncthreads();

        #pragma unroll
        for (int ks = 0; ks < BK; ks += 16) {
            uint32_t af[4][4];
            uint32_t bfr[8][2];
            {
                int jj = lane >> 3, r = lane & 7;
                int m_off = (jj & 1) * 8, k_off = (jj >> 1) * 8;
                #pragma unroll
                for (int mt = 0; mt < 4; mt++) {
                    uint32_t addr = (uint32_t)__cvta_generic_to_shared(
                        &As[ks + k_off + r][wm * 64 + mt * 16 + m_off]);
                    asm volatile("ldmatrix.sync.aligned.m8n8.x4.trans.shared.b16 {%0,%1,%2,%3}, [%4];"
                                 : "=r"(af[mt][0]), "=r"(af[mt][1]), "=r"(af[mt][2]), "=r"(af[mt][3])
                                 : "r"(addr));
                }
                int jb = (lane >> 3) & 1;
                #pragma unroll
                for (int nt = 0; nt < 8; nt++) {
                    uint32_t addr = (uint32_t)__cvta_generic_to_shared(
                        &Bs[wn * 64 + nt * 8 + r][ks + jb * 8]);
                    asm volatile("ldmatrix.sync.aligned.m8n8.x2.shared.b16 {%0,%1}, [%2];"
                                 : "=r"(bfr[nt][0]), "=r"(bfr[nt][1])
                                 : "r"(addr));
                }
            }
            #pragma unroll
            for (int mt = 0; mt < 4; mt++)
                #pragma unroll
                for (int nt = 0; nt < 8; nt++) {
                    asm volatile("mma.sync.aligned.m16n8k16.row.col.f32.bf16.bf16.f32 "
                                 "{%0,%1,%2,%3}, {%4,%5,%6,%7}, {%8,%9}, {%0,%1,%2,%3};"
                                 : "+f"(acc[mt][nt][0]), "+f"(acc[mt][nt][1]),
                                   "+f"(acc[mt][nt][2]), "+f"(acc[mt][nt][3])
                                 : "r"(af[mt][0]), "r"(af[mt][1]), "r"(af[mt][2]), "r"(af[mt][3]),
                                   "r"(bfr[nt][0]), "r"(bfr[nt][1]));
                }
        }
        __syncthreads();
    }

    // Epilogue: write bf16 channel-last pix
    const int mrow = lane >> 2;
    const int ncol = (lane & 3) * 2;
    #pragma unroll
    for (int mt = 0; mt < 4; mt++) {
        #pragma unroll
        for (int nt = 0; nt < 8; nt++) {
            int m = wm * 64 + mt * 16 + mrow;
            int n = wn * 64 + nt * 8 + ncol;
            size_t base = ((size_t)(b * HW + p0 + m)) * CPT + n;
            *reinterpret_cast<__nv_bfloat162*>(&g_pix[base]) =
                __float22bfloat162_rn(make_float2(acc[mt][nt][0], acc[mt][nt][1]));
            *reinterpret_cast<__nv_bfloat162*>(&g_pix[base + 8 * CPT]) =
                __float22bfloat162_rn(make_float2(acc[mt][nt][2], acc[mt][nt][3]));
        }
    }
}

// ---------------------------------------------------------------------------
// Kernel 2: per-point projection + bilinear combine of precomputed pix + bias
//   One warp per point: 4 corner rows of 256 bf16 (contiguous 512B each).
//   out[n,c] = point_feat[n,c] + (sum_corners w_c * pix[corner,c]) + align_b[c]
//   Invalid point / OOB corner -> zero contribution (bias still added, matching ref).
// ---------------------------------------------------------------------------
__global__ void fuse_kernel(const float* __restrict__ pf,
                            const float* __restrict__ centers,
                            const float* __restrict__ P2,
                            const float* __restrict__ R0,
                            const float* __restrict__ Tr,
                            const float* __restrict__ bias,
                            const int*   __restrict__ bidx,
                            float* __restrict__ out) {
    const int gw   = (blockIdx.x * blockDim.x + threadIdx.x) >> 5;
    const int lane = threadIdx.x & 31;
    if (gw >= NPTS) return;
    const int n = gw;
    const int b = bidx[n];

    const float px = centers[n * 3 + 0];
    const float py = centers[n * 3 + 1];
    const float pz = centers[n * 3 + 2];
    const float* tr = Tr + b * 16;
    const float* r0 = R0 + b * 16;
    const float* p2 = P2 + b * 12;

    float cam[4], rect[4], im[3];
    #pragma unroll
    for (int i = 0; i < 4; i++)
        cam[i] = tr[i*4+0]*px + tr[i*4+1]*py + tr[i*4+2]*pz + tr[i*4+3];
    #pragma unroll
    for (int i = 0; i < 4; i++)
        rect[i] = r0[i*4+0]*cam[0] + r0[i*4+1]*cam[1] + r0[i*4+2]*cam[2] + r0[i*4+3]*cam[3];
    #pragma unroll
    for (int i = 0; i < 3; i++)
        im[i] = p2[i*4+0]*rect[0] + p2[i*4+1]*rect[1] + p2[i*4+2]*rect[2] + p2[i*4+3]*rect[3];

    const float zc    = im[2];
    const float depth = fmaxf(zc, 1e-5f);
    const float u     = im[0] / depth;
    const float v     = im[1] / depth;
    const bool valid  = (zc > 0.f) && (u >= 0.f) && (u < (float)IMW) && (v >= 0.f) && (v < (float)IMH);

    const float x0f = floorf(u), y0f = floorf(v);
    const float wx1 = u - x0f, wx0 = 1.f - wx1;
    const float wy1 = v - y0f, wy0 = 1.f - wy1;
    const int xi0 = (int)x0f, yi0 = (int)y0f;

    const float cw[4] = {wx0 * wy0, wx1 * wy0, wx0 * wy1, wx1 * wy1};
    float wgt[4];
    const __nv_bfloat16* rp[4];
    #pragma unroll
    for (int k = 0; k < 4; k++) {
        int xi = xi0 + (k & 1);
        int yi = yi0 + (k >> 1);
        bool inb = (xi >= 0) && (xi <= IMW - 1) && (yi >= 0) && (yi <= IMH - 1);
        wgt[k] = (valid && inb) ? cw[k] : 0.f;
        int xc = min(max(xi, 0), IMW - 1);
        int yc = min(max(yi, 0), IMH - 1);
        rp[k] = &g_pix[((size_t)((b * IMH + yc) * IMW + xc)) * CPT];
    }

    const float* pfrow = pf + (size_t)n * CPT;
    float*       orow  = out + (size_t)n * CPT;
    #pragma unroll
    for (int it = 0; it < 4; it++) {
        int c = it * 64 + lane * 2;
        float a0 = 0.f, a1 = 0.f;
        #pragma unroll
        for (int k = 0; k < 4; k++) {
            if (wgt[k] != 0.f) {
                __nv_bfloat162 pv = *reinterpret_cast<const __nv_bfloat162*>(rp[k] + c);
                float2 pv2 = __bfloat1622float2(pv);
                a0 = fmaf(wgt[k], pv2.x, a0);
                a1 = fmaf(wgt[k], pv2.y, a1);
            }
        }
        float2 pfv = *reinterpret_cast<const float2*>(pfrow + c);
        float2 o;
        o.x = pfv.x + (a0 + bias[c]);
        o.y = pfv.y + (a1 + bias[c + 1]);
        *reinterpret_cast<float2*>(orow + c) = o;
    }
}

// ---------------------------------------------------------------------------
// Launch
// ---------------------------------------------------------------------------
extern "C" void kernel_launch(void* const* d_in, const int* in_sizes, int n_in,
                              void* d_out, int out_size) {
    const float* point_feat = (const float*)d_in[0];
    const float* centers    = (const float*)d_in[1];
    const float* img_feat   = (const float*)d_in[2];
    const float* P2         = (const float*)d_in[3];
    const float* R0         = (const float*)d_in[4];
    const float* Tr         = (const float*)d_in[5];
    const float* align_w    = (const float*)d_in[6];
    const float* align_b    = (const float*)d_in[7];
    const int*   bidx       = (const int*)d_in[8];
    // d_in[9]=img_h, d_in[10]=img_w : fixed at 48/160 for this problem (compile-time)
    float* out = (float*)d_out;

    convW_kernel<<<(CPT * CIMG + 255) / 256, 256>>>(align_w);
    gemm_pix_kernel<<<dim3(HW / BM, 1, BSZ), 256>>>(img_feat);
    fuse_kernel<<<(NPTS + 7) / 8, 256>>>(point_feat, centers, P2, R0, Tr, align_b, bidx, out);
}